// round 14
// baseline (speedup 1.0000x reference)
#include <cuda_runtime.h>
#include <math.h>

// B=16, K=16 steps, N=1024, D=256, L=8.  Rows = B*L = 128.  8 n-chunks of 128.
#define S_ELEMS (16*16*8*256)
#define QT_PLANE (128*1024)
#define GI_PLANE (128*768)
#define H1_PLANE (128*256)
#define UP_PLANE (128*256)
#define NB 128           // persistent blocks (< 148 SMs -> co-resident, barrier-safe)

// ---------------- scratch ----------------
__device__ __align__(16) float g_slots[128*256];
__device__ __align__(16) float g_Mcomb[256*1024];   // [k][0:256]=Wq^T Wk*scale, [k][256:1024]=W_hh^T
__device__ __align__(16) float g_cpart[8*1024];     // 8 e-partials of [scale*bq@Wk | b_hh]
__device__ __align__(16) float g_M2[768*256];       // W_ih @ Wv
__device__ __align__(16) float g_c2part[8*768];     // 8 e-partials of (W_ih@bv + b_ih)
__device__ __align__(16) float g_qtgh2[2*QT_PLANE]; // 2 K-split partials of [Qt | gh]
__device__ __align__(16) float g_escore[128*1024];  // exp(score - chunkmax)
__device__ __align__(16) float g_pmax[128*8];
__device__ __align__(16) float g_psum[128*8];
__device__ __align__(16) float g_upart[8*UP_PLANE]; // UNnormalized expP@H partials per n-chunk
__device__ __align__(16) float g_gi2[2*GI_PLANE];   // 2 K-split partials of gi
__device__ __align__(16) float g_s2[128*256];
__device__ __align__(16) float g_h1p[8*H1_PLANE];   // 8 K-split partials of ffn1 pre-activation
__device__ __align__(16) float g_h2p[8*H1_PLANE];   // 8 K-split partials of ffn2
__device__ unsigned g_barcnt;

__device__ __forceinline__ float sigm(float x) { return 1.f / (1.f + expf(-x)); }

// ============ 32x32-tile GEMM body (precompute only) ============
template<int AT>
__device__ __forceinline__ void gemm_body(
    int m0, int c0,
    const float* __restrict__ A, int lda,
    const float* __restrict__ B, int ldb,
    float* __restrict__ C, int ldc, float alpha)
{
    __shared__ float As[32][33];
    __shared__ __align__(16) float Bs[32][36];
    const int tid = threadIdx.x;
    const int row = tid & 31, cg = tid >> 5;
    float a0 = 0.f, a1 = 0.f, a2 = 0.f, a3 = 0.f;
    for (int k0 = 0; k0 < 256; k0 += 32) {
        if (AT) {
            int r = tid & 31, e = tid >> 5;
            #pragma unroll
            for (int i = 0; i < 4; i++) { int ee = e + i*8; As[r][ee] = A[(size_t)(k0+ee)*lda + m0 + r]; }
        } else {
            int e = tid & 31, r = tid >> 5;
            #pragma unroll
            for (int i = 0; i < 4; i++) { int rr = r + i*8; As[rr][e] = A[(size_t)(m0+rr)*lda + k0 + e]; }
        }
        {
            int c = tid & 31, e = tid >> 5;
            #pragma unroll
            for (int i = 0; i < 4; i++) { int ee = e + i*8; Bs[ee][c] = B[(size_t)(k0+ee)*ldb + c0 + c]; }
        }
        __syncthreads();
        #pragma unroll
        for (int e = 0; e < 32; e++) {
            float a = As[row][e];
            float4 b4 = *(const float4*)&Bs[e][cg*4];
            a0 = fmaf(a,b4.x,a0); a1 = fmaf(a,b4.y,a1); a2 = fmaf(a,b4.z,a2); a3 = fmaf(a,b4.w,a3);
        }
        __syncthreads();
    }
    int cb = c0 + cg*4;
    *(float4*)&C[(size_t)(m0+row)*ldc + cb] = make_float4(a0*alpha, a1*alpha, a2*alpha, a3*alpha);
}

// ================= precompute (2 kernels) =================
__global__ void pre_misc(const float* __restrict__ eps, const float* __restrict__ mu,
                         const float* __restrict__ ls, const float* __restrict__ W_hh,
                         const float* __restrict__ bq, const float* __restrict__ Wk,
                         const float* __restrict__ b_hh, const float* __restrict__ W_ih,
                         const float* __restrict__ bv, const float* __restrict__ b_ih)
{
    const int bx = blockIdx.x, tid = threadIdx.x;
    if (bx == 0 && tid == 0) g_barcnt = 0;          // reset megakernel barrier
    if (bx < 128) {
        int i = bx * 256 + tid;
        int ld = i & 2047;
        g_slots[i] = mu[ld] + expf(ls[ld]) * eps[i];
    } else if (bx < 896) {
        int idx = (bx - 128) * 256 + tid;           // 256x768
        int c = idx >> 8, k = idx & 255;
        g_Mcomb[k * 1024 + 256 + c] = W_hh[c * 256 + k];
    } else if (bx < 928) {
        int q = bx - 896;
        int p = q >> 2;
        int c = (q & 3) * 256 + tid;
        if (c < 256) {
            int e0 = p * 32;
            float s = 0.f;
            #pragma unroll 8
            for (int e = 0; e < 32; e++) s = fmaf(bq[e0+e], Wk[(e0+e)*256 + c], s);
            g_cpart[p * 1024 + c] = s * 0.0625f;
        } else {
            g_cpart[p * 1024 + c] = (p == 0) ? b_hh[c - 256] : 0.f;
        }
    } else {
        int q = bx - 928;
        int p = q / 3;
        int c = (q % 3) * 256 + tid;
        int e0 = p * 32;
        float s = (p == 0) ? b_ih[c] : 0.f;
        #pragma unroll 8
        for (int e = 0; e < 32; e++) s = fmaf(W_ih[c*256 + e0+e], bv[e0+e], s);
        g_c2part[p * 768 + c] = s;
    }
}

__global__ void pre_gemm(const float* __restrict__ Wq, const float* __restrict__ Wk,
                         const float* __restrict__ W_ih, const float* __restrict__ Wv)
{
    if (blockIdx.y < 8)
        gemm_body<1>(blockIdx.y*32, blockIdx.x*32, Wq,256, Wk,256, g_Mcomb,1024, 0.0625f);
    else
        gemm_body<0>((blockIdx.y-8)*32, blockIdx.x*32, W_ih,256, Wv,256, g_M2,256, 1.f);
}

// ================= persistent megakernel =================
__global__ void __launch_bounds__(512)
mega_kernel(const float* __restrict__ H,
            const float* __restrict__ W1, const float* __restrict__ b1,
            const float* __restrict__ W2, const float* __restrict__ b2,
            const float* __restrict__ lg, const float* __restrict__ lb,
            float* __restrict__ outS, float* __restrict__ outB)
{
    __shared__ __align__(16) float sm[10528];       // 42.1 KB, carved per phase
    const int bid = blockIdx.x, tid = threadIdx.x;
    unsigned nbar = 0;

    auto gridbar = [&]() {
        __threadfence();
        __syncthreads();
        if (tid == 0) {
            atomicAdd(&g_barcnt, 1u);
            unsigned target = (nbar + 1) * NB;
            while (*(volatile unsigned*)&g_barcnt < target) { }
            __threadfence();
        }
        nbar++;
        __syncthreads();
    };

    #pragma unroll 1
    for (int t = 0; t < 16; t++) {
        // ---------- Phase A: qtgh partials, block-cooperative 16x128 tile, k=128 ----------
        {
            const int ks = bid & 1, colH = (bid >> 1) & 7, rowT = bid >> 4;
            const int m0 = rowT*16, c0 = colH*128, kb = ks*128;
            float* Ss = sm;              // slots tile k-major [128][17] -> 2174
            float* Bs = sm + 2176;       // Mcomb fragment [32][132] = 4224
            for (int i = tid; i < 2048; i += 512) {
                int r = i >> 7, k = i & 127;
                Ss[k*17 + r] = __ldcg(&g_slots[(m0+r)*256 + kb + k]);
            }
            const int row = tid & 15, cg = tid >> 4;
            float a0=0.f, a1=0.f, a2=0.f, a3=0.f;
            for (int k0 = 0; k0 < 128; k0 += 32) {
                __syncthreads();
                for (int i = tid; i < 4096; i += 512) {
                    int e = i >> 7, c = i & 127;
                    Bs[e*132 + c] = g_Mcomb[(size_t)(kb+k0+e)*1024 + c0 + c];
                }
                __syncthreads();
                #pragma unroll
                for (int e = 0; e < 32; e++) {
                    float a = Ss[(k0+e)*17 + row];
                    float4 b4 = *(const float4*)&Bs[e*132 + cg*4];
                    a0 = fmaf(a,b4.x,a0); a1 = fmaf(a,b4.y,a1);
                    a2 = fmaf(a,b4.z,a2); a3 = fmaf(a,b4.w,a3);
                }
            }
            int cb = c0 + cg*4;
            if (ks == 0) {
                #pragma unroll
                for (int p = 0; p < 8; p++) {
                    const float* bp = g_cpart + p * 1024;
                    a0 += bp[cb]; a1 += bp[cb+1]; a2 += bp[cb+2]; a3 += bp[cb+3];
                }
            }
            *(float4*)&g_qtgh2[(size_t)ks*QT_PLANE + (m0+row)*1024 + cb] = make_float4(a0,a1,a2,a3);
        }
        gridbar();

        // ---------- Phase B: scores + chunk stats + exp·H partials (1 task/block) ----------
        {
            const int b = bid >> 3, chunk = bid & 7, n0 = chunk * 128;
            float* Qs    = sm;                       // 2048
            float* attnS = sm + 2048;                // 1024
            float* redM  = sm + 3072;                // 32
            float* redS  = sm + 3104;                // 32
            float* mrow  = sm + 3136;                // 8
            const int nl = tid & 127, sg = tid >> 7, lane = tid & 31, w = tid >> 5;

            {   // Q = sum of 2 qtgh k-partials
                int s = tid >> 6, d4 = tid & 63;
                float4 x0 = __ldcg((const float4*)&g_qtgh2[(size_t)(b*8+s)*1024 + d4*4]);
                float4 x1 = __ldcg((const float4*)&g_qtgh2[QT_PLANE + (size_t)(b*8+s)*1024 + d4*4]);
                *(float4*)&Qs[s*256 + d4*4] = make_float4(x0.x+x1.x, x0.y+x1.y, x0.z+x1.z, x0.w+x1.w);
            }
            __syncthreads();

            const float4* hrow = (const float4*)(H + ((size_t)(b*16 + t)*1024 + n0 + nl) * 256);
            float a0 = 0.f, a1 = 0.f;
            #pragma unroll 8
            for (int d4 = 0; d4 < 64; d4++) {
                float4 h4 = __ldg(&hrow[d4]);
                float4 q0 = *(const float4*)&Qs[(sg*2+0)*256 + d4*4];
                float4 q1 = *(const float4*)&Qs[(sg*2+1)*256 + d4*4];
                a0 = fmaf(h4.x,q0.x,a0); a0 = fmaf(h4.y,q0.y,a0);
                a0 = fmaf(h4.z,q0.z,a0); a0 = fmaf(h4.w,q0.w,a0);
                a1 = fmaf(h4.x,q1.x,a1); a1 = fmaf(h4.y,q1.y,a1);
                a1 = fmaf(h4.z,q1.z,a1); a1 = fmaf(h4.w,q1.w,a1);
            }
            #pragma unroll
            for (int i = 0; i < 2; i++) {
                float m = i ? a1 : a0;
                #pragma unroll
                for (int o = 16; o > 0; o >>= 1) m = fmaxf(m, __shfl_xor_sync(0xffffffffu, m, o));
                if (lane == 0) redM[(sg*2+i)*4 + (w & 3)] = m;
            }
            __syncthreads();
            if (tid < 8) {
                float m = fmaxf(fmaxf(redM[tid*4], redM[tid*4+1]), fmaxf(redM[tid*4+2], redM[tid*4+3]));
                mrow[tid] = m;
                g_pmax[(b*8 + tid)*8 + chunk] = m;
            }
            __syncthreads();
            float e0v = expf(a0 - mrow[sg*2+0]);
            float e1v = expf(a1 - mrow[sg*2+1]);
            g_escore[(size_t)(b*8 + sg*2+0)*1024 + n0 + nl] = e0v;
            g_escore[(size_t)(b*8 + sg*2+1)*1024 + n0 + nl] = e1v;
            attnS[(sg*2+0)*128 + nl] = e0v;
            attnS[(sg*2+1)*128 + nl] = e1v;
            #pragma unroll
            for (int i = 0; i < 2; i++) {
                float e = i ? e1v : e0v;
                #pragma unroll
                for (int o = 16; o > 0; o >>= 1) e += __shfl_xor_sync(0xffffffffu, e, o);
                if (lane == 0) redS[(sg*2+i)*4 + (w & 3)] = e;
            }
            __syncthreads();
            if (tid < 8)
                g_psum[(b*8 + tid)*8 + chunk] = redS[tid*4] + redS[tid*4+1] + redS[tid*4+2] + redS[tid*4+3];

            const int j = tid & 255, sh = tid >> 8;
            const float* hb = H + ((size_t)(b*16 + t)*1024 + n0) * 256;
            float acc[4] = {0.f,0.f,0.f,0.f};
            #pragma unroll 8
            for (int n = 0; n < 128; n++) {
                float hv = __ldg(&hb[(size_t)n*256 + j]);
                #pragma unroll
                for (int s = 0; s < 4; s++) acc[s] = fmaf(attnS[(sh*4+s)*128 + n], hv, acc[s]);
            }
            float* up = g_upart + (size_t)chunk * UP_PLANE;
            #pragma unroll
            for (int s = 0; s < 4; s++) up[(b*8 + sh*4 + s)*256 + j] = acc[s];
        }
        gridbar();

        // ---------- Phase C: gi partials, block-cooperative 16x128 tile (96 blocks) ----------
        {
            bool act = bid < 96;
            int tb = act ? bid : 0;
            const int ks = tb & 1, colT = (tb >> 1) % 6, rowT = (tb >> 1) / 6;
            const int m0 = rowT*16, c0 = colT*128, kb = ks*128;
            float* Ss = sm;              // flash-combined U tile k-major [128][17]
            float* Bs = sm + 2176;       // M2 fragment [32][132]
            float* ws = sm + 6400;       // [16][9]
            if (tid < 16) {
                int r = m0 + tid;
                float pm[8];
                #pragma unroll
                for (int c = 0; c < 8; c++) pm[c] = __ldcg(&g_pmax[r*8 + c]);
                float m = pm[0];
                #pragma unroll
                for (int c = 1; c < 8; c++) m = fmaxf(m, pm[c]);
                float S = 0.f;
                #pragma unroll
                for (int c = 0; c < 8; c++) S += __ldcg(&g_psum[r*8 + c]) * expf(pm[c] - m);
                float invS = 1.f / S;
                #pragma unroll
                for (int c = 0; c < 8; c++) ws[tid*9 + c] = expf(pm[c] - m) * invS;
            }
            __syncthreads();
            for (int i = tid; i < 2048; i += 512) {
                int r = i >> 7, k = i & 127;
                size_t idx = (size_t)(m0+r)*256 + kb + k;
                float v = 0.f;
                #pragma unroll
                for (int p = 0; p < 8; p++)
                    v = fmaf(__ldcg(&g_upart[(size_t)p*UP_PLANE + idx]), ws[r*9 + p], v);
                Ss[k*17 + r] = v;
            }
            const int row = tid & 15, cg = tid >> 4;
            float a0=0.f, a1=0.f, a2=0.f, a3=0.f;
            for (int k0 = 0; k0 < 128; k0 += 32) {
                __syncthreads();
                for (int i = tid; i < 4096; i += 512) {
                    int e = i >> 7, c = i & 127;
                    Bs[e*132 + c] = g_M2[(size_t)(c0+c)*256 + kb + k0 + e];
                }
                __syncthreads();
                #pragma unroll
                for (int e = 0; e < 32; e++) {
                    float a = Ss[(k0+e)*17 + row];
                    float4 b4 = *(const float4*)&Bs[e*132 + cg*4];
                    a0 = fmaf(a,b4.x,a0); a1 = fmaf(a,b4.y,a1);
                    a2 = fmaf(a,b4.z,a2); a3 = fmaf(a,b4.w,a3);
                }
            }
            int cb = c0 + cg*4;
            if (ks == 0) {
                #pragma unroll
                for (int p = 0; p < 8; p++) {
                    const float* bp = g_c2part + p * 768;
                    a0 += bp[cb]; a1 += bp[cb+1]; a2 += bp[cb+2]; a3 += bp[cb+3];
                }
            }
            if (act)
                *(float4*)&g_gi2[(size_t)ks*GI_PLANE + (m0+row)*768 + cb] = make_float4(a0,a1,a2,a3);
        }
        gridbar();

        // ---------- Phase D: GRU (once per element) + ffn1 partials + Beta writer ----------
        {
            const int colH = bid & 1, ks = (bid >> 1) & 7, rowT = bid >> 4;
            const int m0 = rowT*16, kb = ks*32, c0 = colH*128;
            float* Ss2 = sm;             // s2 tile k-major [32][17] = 544
            float* Bs  = sm + 544;       // W1 fragment [32][132] = 4224
            float* ws8 = sm + 4768;      // 8 beta weights for row bid
            {   // s2: one element per thread
                int r = tid >> 5, k = tid & 31, gr = m0 + r, d = kb + k;
                float gir = __ldcg(&g_gi2[gr*768 + d])       + __ldcg(&g_gi2[GI_PLANE + gr*768 + d]);
                float giz = __ldcg(&g_gi2[gr*768 + 256 + d]) + __ldcg(&g_gi2[GI_PLANE + gr*768 + 256 + d]);
                float gin = __ldcg(&g_gi2[gr*768 + 512 + d]) + __ldcg(&g_gi2[GI_PLANE + gr*768 + 512 + d]);
                float ghr = __ldcg(&g_qtgh2[gr*1024 + 256 + d]) + __ldcg(&g_qtgh2[QT_PLANE + gr*1024 + 256 + d]);
                float ghz = __ldcg(&g_qtgh2[gr*1024 + 512 + d]) + __ldcg(&g_qtgh2[QT_PLANE + gr*1024 + 512 + d]);
                float ghn = __ldcg(&g_qtgh2[gr*1024 + 768 + d]) + __ldcg(&g_qtgh2[QT_PLANE + gr*1024 + 768 + d]);
                float rg = sigm(gir + ghr);
                float z  = sigm(giz + ghz);
                float nn = tanhf(gin + rg * ghn);
                float s2 = (1.f - z) * nn + z * __ldcg(&g_slots[gr*256 + d]);
                Ss2[k*17 + r] = s2;
                if (colH == 0) g_s2[gr*256 + d] = s2;
            }
            if (tid < 8) {               // beta weights for row bid
                int r = bid;
                float pm[8];
                #pragma unroll
                for (int c = 0; c < 8; c++) pm[c] = __ldcg(&g_pmax[r*8 + c]);
                float m = pm[0];
                #pragma unroll
                for (int c = 1; c < 8; c++) m = fmaxf(m, pm[c]);
                float S = 0.f;
                #pragma unroll
                for (int c = 0; c < 8; c++) S += __ldcg(&g_psum[r*8 + c]) * expf(pm[c] - m);
                ws8[tid] = expf(pm[tid] - m) / S;
            }
            for (int i = tid; i < 4096; i += 512) {
                int e = i >> 7, c = i & 127;
                Bs[e*132 + c] = W1[(size_t)(c0+c)*256 + kb + e];
            }
            __syncthreads();
            if (tid < 256) {             // Beta writer: row bid, one float4 per thread
                float wv = ws8[tid >> 5];
                float4 v = __ldcg((const float4*)&g_escore[(size_t)bid*1024 + tid*4]);
                int bb = bid >> 3, l = bid & 7;
                *(float4*)&outB[(size_t)((bb*16 + t)*8 + l)*1024 + tid*4] =
                    make_float4(v.x*wv, v.y*wv, v.z*wv, v.w*wv);
            }
            const int row = tid & 15, cg = tid >> 4;
            float a0=0.f, a1=0.f, a2=0.f, a3=0.f;
            #pragma unroll
            for (int e = 0; e < 32; e++) {
                float a = Ss2[e*17 + row];
                float4 b4 = *(const float4*)&Bs[e*132 + cg*4];
                a0 = fmaf(a,b4.x,a0); a1 = fmaf(a,b4.y,a1);
                a2 = fmaf(a,b4.z,a2); a3 = fmaf(a,b4.w,a3);
            }
            int cb = c0 + cg*4;
            if (ks == 0) { a0 += b1[cb]; a1 += b1[cb+1]; a2 += b1[cb+2]; a3 += b1[cb+3]; }
            *(float4*)&g_h1p[(size_t)ks*H1_PLANE + (m0+row)*256 + cb] = make_float4(a0,a1,a2,a3);
        }
        gridbar();

        // ---------- Phase E1: ffn2 partials (relu-summed h1 tile @ W2 fragment) ----------
        {
            const int colH = bid & 1, ks = (bid >> 1) & 7, rowT = bid >> 4;
            const int m0 = rowT*16, kb = ks*32, c0 = colH*128;
            float* Sh = sm;              // relu(h1) tile k-major [32][17]
            float* Bs = sm + 544;        // W2 fragment [32][132]
            {   // one element per thread: relu of 8-plane sum
                int r = tid >> 5, k = tid & 31;
                size_t off = (size_t)(m0 + r)*256 + kb + k;
                float v = 0.f;
                #pragma unroll
                for (int p = 0; p < 8; p++) v += __ldcg(&g_h1p[(size_t)p*H1_PLANE + off]);
                Sh[k*17 + r] = fmaxf(v, 0.f);
            }
            for (int i = tid; i < 4096; i += 512) {
                int e = i >> 7, c = i & 127;
                Bs[e*132 + c] = W2[(size_t)(c0+c)*256 + kb + e];
            }
            __syncthreads();
            const int row = tid & 15, cg = tid >> 4;
            float a0=0.f, a1=0.f, a2=0.f, a3=0.f;
            #pragma unroll
            for (int e = 0; e < 32; e++) {
                float a = Sh[e*17 + row];
                float4 b4 = *(const float4*)&Bs[e*132 + cg*4];
                a0 = fmaf(a,b4.x,a0); a1 = fmaf(a,b4.y,a1);
                a2 = fmaf(a,b4.z,a2); a3 = fmaf(a,b4.w,a3);
            }
            int cb = c0 + cg*4;
            *(float4*)&g_h2p[(size_t)ks*H1_PLANE + (m0+row)*256 + cb] = make_float4(a0,a1,a2,a3);
        }
        gridbar();

        // ---------- Phase E2: sum partials + residual + LN (64 blocks, 2 rows) ----------
        {
            bool act = bid < 64;
            int rb = (act ? bid : 0) * 2;
            float* rs = sm;              // 16
            float* rq = sm + 16;         // 16
            const int w = tid >> 5, lane = tid & 31;
            const int rr = w >> 3, oct = w & 7;
            const int rowr = rb + rr, col = oct*32 + lane;
            size_t off = (size_t)rowr*256 + col;
            float x = 0.f;
            #pragma unroll
            for (int p = 0; p < 8; p++) x += __ldcg(&g_h2p[(size_t)p*H1_PLANE + off]);
            x += b2[col] + __ldcg(&g_s2[off]);
            float s = x, q = x*x;
            #pragma unroll
            for (int o = 16; o > 0; o >>= 1) {
                s += __shfl_xor_sync(0xffffffffu, s, o);
                q += __shfl_xor_sync(0xffffffffu, q, o);
            }
            __syncthreads();
            if (lane == 0) { rs[rr*8 + oct] = s; rq[rr*8 + oct] = q; }
            __syncthreads();
            float ts = 0.f, tq = 0.f;
            #pragma unroll
            for (int o = 0; o < 8; o++) { ts += rs[rr*8 + o]; tq += rq[rr*8 + o]; }
            float mean = ts * (1.f/256.f);
            float var  = tq * (1.f/256.f) - mean*mean;
            float inv  = rsqrtf(var + 1e-5f);
            if (act) {
                float y = (x - mean) * inv * lg[col] + lb[col];
                g_slots[off] = y;
                int bb = rowr >> 3, l = rowr & 7;
                outS[(size_t)((bb*16 + t)*8 + l)*256 + col] = y;
            }
        }
        gridbar();
    }
}

// ================= launcher =================
extern "C" void kernel_launch(void* const* d_in, const int* in_sizes, int n_in,
                              void* d_out, int out_size)
{
    const float* H    = (const float*)d_in[0];
    const float* eps  = (const float*)d_in[1];
    const float* mu   = (const float*)d_in[2];
    const float* ls   = (const float*)d_in[3];
    const float* Wq   = (const float*)d_in[4];
    const float* bq   = (const float*)d_in[5];
    const float* Wk   = (const float*)d_in[6];
    // d_in[7] = bk: row-constant in logits, cancels in softmax — provably unused.
    const float* Wv   = (const float*)d_in[8];
    const float* bv   = (const float*)d_in[9];
    const float* W_ih = (const float*)d_in[10];
    const float* b_ih = (const float*)d_in[11];
    const float* W_hh = (const float*)d_in[12];
    const float* b_hh = (const float*)d_in[13];
    const float* W1   = (const float*)d_in[14];
    const float* b1   = (const float*)d_in[15];
    const float* W2   = (const float*)d_in[16];
    const float* b2   = (const float*)d_in[17];
    const float* lng  = (const float*)d_in[18];
    const float* lnb  = (const float*)d_in[19];

    float* outS = (float*)d_out;
    float* outB = outS + S_ELEMS;

    pre_misc<<<952, 256>>>(eps, mu, ls, W_hh, bq, Wk, b_hh, W_ih, bv, b_ih);
    pre_gemm<<<dim3(8, 32), 256>>>(Wq, Wk, W_ih, Wv);
    mega_kernel<<<NB, 512>>>(H, W1, b1, W2, b2, lng, lnb, outS, outB);
}

// round 15
// speedup vs baseline: 1.0065x; 1.0065x over previous
#include <cuda_runtime.h>
#include <math.h>

// B=16, K=16 steps, N=1024, D=256, L=8.  Rows = B*L = 128.  8 n-chunks of 128.
#define S_ELEMS (16*16*8*256)
#define QT_PLANE (128*1024)
#define GI_PLANE (128*768)
#define H1_PLANE (128*256)
#define UP_PLANE (128*256)
#define NB 128           // persistent blocks (< 148 SMs -> co-resident, barrier-safe)

// ---------------- scratch ----------------
__device__ __align__(16) float g_slots[128*256];
__device__ __align__(16) float g_Mcomb[256*1024];   // [k][0:256]=Wq^T Wk*scale, [k][256:1024]=W_hh^T
__device__ __align__(16) float g_cpart[8*1024];     // 8 e-partials of [scale*bq@Wk | b_hh]
__device__ __align__(16) float g_M2[768*256];       // W_ih @ Wv
__device__ __align__(16) float g_c2part[8*768];     // 8 e-partials of (W_ih@bv + b_ih)
__device__ __align__(16) float g_qtgh2[2*QT_PLANE]; // 2 K-split partials of [Qt | gh]
__device__ __align__(16) float g_escore[128*1024];  // exp(score - chunkmax)
__device__ __align__(16) float g_pmax[128*8];
__device__ __align__(16) float g_psum[128*8];
__device__ __align__(16) float g_upart[8*UP_PLANE]; // UNnormalized expP@H partials per n-chunk
__device__ __align__(16) float g_gi2[2*GI_PLANE];   // 2 K-split partials of gi
__device__ __align__(16) float g_s2[128*256];
__device__ __align__(16) float g_h1p[8*H1_PLANE];   // 8 K-split partials of ffn1 pre-activation
__device__ __align__(16) float g_h2p[8*H1_PLANE];   // 8 K-split partials of ffn2
__device__ unsigned g_barcnt;

__device__ __forceinline__ float sigm(float x) { return 1.f / (1.f + expf(-x)); }

// ============ 32x32-tile GEMM body (precompute only) ============
template<int AT>
__device__ __forceinline__ void gemm_body(
    int m0, int c0,
    const float* __restrict__ A, int lda,
    const float* __restrict__ B, int ldb,
    float* __restrict__ C, int ldc, float alpha)
{
    __shared__ float As[32][33];
    __shared__ __align__(16) float Bs[32][36];
    const int tid = threadIdx.x;
    const int row = tid & 31, cg = tid >> 5;
    float a0 = 0.f, a1 = 0.f, a2 = 0.f, a3 = 0.f;
    for (int k0 = 0; k0 < 256; k0 += 32) {
        if (AT) {
            int r = tid & 31, e = tid >> 5;
            #pragma unroll
            for (int i = 0; i < 4; i++) { int ee = e + i*8; As[r][ee] = A[(size_t)(k0+ee)*lda + m0 + r]; }
        } else {
            int e = tid & 31, r = tid >> 5;
            #pragma unroll
            for (int i = 0; i < 4; i++) { int rr = r + i*8; As[rr][e] = A[(size_t)(m0+rr)*lda + k0 + e]; }
        }
        {
            int c = tid & 31, e = tid >> 5;
            #pragma unroll
            for (int i = 0; i < 4; i++) { int ee = e + i*8; Bs[ee][c] = B[(size_t)(k0+ee)*ldb + c0 + c]; }
        }
        __syncthreads();
        #pragma unroll
        for (int e = 0; e < 32; e++) {
            float a = As[row][e];
            float4 b4 = *(const float4*)&Bs[e][cg*4];
            a0 = fmaf(a,b4.x,a0); a1 = fmaf(a,b4.y,a1); a2 = fmaf(a,b4.z,a2); a3 = fmaf(a,b4.w,a3);
        }
        __syncthreads();
    }
    int cb = c0 + cg*4;
    *(float4*)&C[(size_t)(m0+row)*ldc + cb] = make_float4(a0*alpha, a1*alpha, a2*alpha, a3*alpha);
}

// ================= precompute (2 kernels) =================
// blocks: [0,128) slots | [128,320) W_hh transpose tiles (24x8 of 32x32) | [320,352) ccomb | [352,376) c2
__global__ void pre_misc(const float* __restrict__ eps, const float* __restrict__ mu,
                         const float* __restrict__ ls, const float* __restrict__ W_hh,
                         const float* __restrict__ bq, const float* __restrict__ Wk,
                         const float* __restrict__ b_hh, const float* __restrict__ W_ih,
                         const float* __restrict__ bv, const float* __restrict__ b_ih)
{
    const int bx = blockIdx.x, tid = threadIdx.x;
    if (bx == 0 && tid == 0) g_barcnt = 0;          // reset megakernel barrier
    if (bx < 128) {
        int i = bx * 256 + tid;
        int ld = i & 2047;
        g_slots[i] = mu[ld] + expf(ls[ld]) * eps[i];
    } else if (bx < 320) {
        // tiled transpose: g_Mcomb[k][256+c] = W_hh[c][k], coalesced both sides
        __shared__ float Ts[32][33];
        int bx2 = bx - 128;
        int tc = (bx2 % 24) * 32, tk = (bx2 / 24) * 32;
        int r = tid >> 5, col = tid & 31;
        #pragma unroll
        for (int i = 0; i < 4; i++) {
            int rr = r + i*8;
            Ts[rr][col] = W_hh[(size_t)(tc + rr) * 256 + tk + col];
        }
        __syncthreads();
        #pragma unroll
        for (int i = 0; i < 4; i++) {
            int kr = r + i*8;
            g_Mcomb[(size_t)(tk + kr) * 1024 + 256 + tc + col] = Ts[col][kr];
        }
    } else if (bx < 352) {
        int q = bx - 320;
        int p = q >> 2;
        int c = (q & 3) * 256 + tid;
        if (c < 256) {
            int e0 = p * 32;
            float s = 0.f;
            #pragma unroll 8
            for (int e = 0; e < 32; e++) s = fmaf(bq[e0+e], Wk[(e0+e)*256 + c], s);
            g_cpart[p * 1024 + c] = s * 0.0625f;
        } else {
            g_cpart[p * 1024 + c] = (p == 0) ? b_hh[c - 256] : 0.f;
        }
    } else {
        int q = bx - 352;
        int p = q / 3;
        int c = (q % 3) * 256 + tid;
        int e0 = p * 32;
        float s = (p == 0) ? b_ih[c] : 0.f;
        #pragma unroll 8
        for (int e = 0; e < 32; e++) s = fmaf(W_ih[c*256 + e0+e], bv[e0+e], s);
        g_c2part[p * 768 + c] = s;
    }
}

__global__ void pre_gemm(const float* __restrict__ Wq, const float* __restrict__ Wk,
                         const float* __restrict__ W_ih, const float* __restrict__ Wv)
{
    if (blockIdx.y < 8)
        gemm_body<1>(blockIdx.y*32, blockIdx.x*32, Wq,256, Wk,256, g_Mcomb,1024, 0.0625f);
    else
        gemm_body<0>((blockIdx.y-8)*32, blockIdx.x*32, W_ih,256, Wv,256, g_M2,256, 1.f);
}

// ================= persistent megakernel =================
__global__ void __launch_bounds__(512)
mega_kernel(const float* __restrict__ H,
            const float* __restrict__ W1, const float* __restrict__ b1,
            const float* __restrict__ W2, const float* __restrict__ b2,
            const float* __restrict__ lg, const float* __restrict__ lb,
            float* __restrict__ outS, float* __restrict__ outB)
{
    __shared__ __align__(16) float sm[10528];       // 42.1 KB, carved per phase
    const int bid = blockIdx.x, tid = threadIdx.x;
    unsigned nbar = 0;

    // CG-style grid barrier: syncthreads edge + tid0 release-add arrival + acquire poll.
    // Cross-phase data is read with __ldcg (L2), so no L1 staleness concerns.
    auto gridbar = [&]() {
        __syncthreads();
        if (tid == 0) {
            unsigned target = (nbar + 1) * NB;
            asm volatile("red.release.gpu.global.add.u32 [%0], 1;"
                         :: "l"(&g_barcnt) : "memory");
            unsigned v;
            do {
                asm volatile("ld.acquire.gpu.global.u32 %0, [%1];"
                             : "=r"(v) : "l"(&g_barcnt) : "memory");
            } while (v < target);
        }
        nbar++;
        __syncthreads();
    };

    #pragma unroll 1
    for (int t = 0; t < 16; t++) {
        // ---------- Phase A: qtgh partials, block-cooperative 16x128 tile, k=128 ----------
        {
            const int ks = bid & 1, colH = (bid >> 1) & 7, rowT = bid >> 4;
            const int m0 = rowT*16, c0 = colH*128, kb = ks*128;
            float* Ss = sm;              // slots tile k-major [128][17]
            float* Bs = sm + 2176;       // Mcomb fragment [32][132]
            for (int i = tid; i < 2048; i += 512) {
                int r = i >> 7, k = i & 127;
                Ss[k*17 + r] = __ldcg(&g_slots[(m0+r)*256 + kb + k]);
            }
            const int row = tid & 15, cg = tid >> 4;
            float a0=0.f, a1=0.f, a2=0.f, a3=0.f;
            for (int k0 = 0; k0 < 128; k0 += 32) {
                __syncthreads();
                for (int i = tid; i < 4096; i += 512) {
                    int e = i >> 7, c = i & 127;
                    Bs[e*132 + c] = g_Mcomb[(size_t)(kb+k0+e)*1024 + c0 + c];
                }
                __syncthreads();
                #pragma unroll
                for (int e = 0; e < 32; e++) {
                    float a = Ss[(k0+e)*17 + row];
                    float4 b4 = *(const float4*)&Bs[e*132 + cg*4];
                    a0 = fmaf(a,b4.x,a0); a1 = fmaf(a,b4.y,a1);
                    a2 = fmaf(a,b4.z,a2); a3 = fmaf(a,b4.w,a3);
                }
            }
            int cb = c0 + cg*4;
            if (ks == 0) {
                #pragma unroll
                for (int p = 0; p < 8; p++) {
                    const float* bp = g_cpart + p * 1024;
                    a0 += bp[cb]; a1 += bp[cb+1]; a2 += bp[cb+2]; a3 += bp[cb+3];
                }
            }
            *(float4*)&g_qtgh2[(size_t)ks*QT_PLANE + (m0+row)*1024 + cb] = make_float4(a0,a1,a2,a3);
        }
        gridbar();

        // ---------- Phase B: scores + chunk stats + exp·H partials (1 task/block) ----------
        {
            const int b = bid >> 3, chunk = bid & 7, n0 = chunk * 128;
            float* Qs    = sm;                       // 2048
            float* attnT = sm + 2048;                // [128][8] transposed exp-scores
            float* redM  = sm + 3072;                // 32
            float* redS  = sm + 3104;                // 32
            float* mrow  = sm + 3136;                // 8
            const int nl = tid & 127, sg = tid >> 7, lane = tid & 31, w = tid >> 5;

            {   // Q = sum of 2 qtgh k-partials
                int s = tid >> 6, d4 = tid & 63;
                float4 x0 = __ldcg((const float4*)&g_qtgh2[(size_t)(b*8+s)*1024 + d4*4]);
                float4 x1 = __ldcg((const float4*)&g_qtgh2[QT_PLANE + (size_t)(b*8+s)*1024 + d4*4]);
                *(float4*)&Qs[s*256 + d4*4] = make_float4(x0.x+x1.x, x0.y+x1.y, x0.z+x1.z, x0.w+x1.w);
            }
            __syncthreads();

            const float4* hrow = (const float4*)(H + ((size_t)(b*16 + t)*1024 + n0 + nl) * 256);
            float a0 = 0.f, a1 = 0.f;
            #pragma unroll 8
            for (int d4 = 0; d4 < 64; d4++) {
                float4 h4 = __ldg(&hrow[d4]);
                float4 q0 = *(const float4*)&Qs[(sg*2+0)*256 + d4*4];
                float4 q1 = *(const float4*)&Qs[(sg*2+1)*256 + d4*4];
                a0 = fmaf(h4.x,q0.x,a0); a0 = fmaf(h4.y,q0.y,a0);
                a0 = fmaf(h4.z,q0.z,a0); a0 = fmaf(h4.w,q0.w,a0);
                a1 = fmaf(h4.x,q1.x,a1); a1 = fmaf(h4.y,q1.y,a1);
                a1 = fmaf(h4.z,q1.z,a1); a1 = fmaf(h4.w,q1.w,a1);
            }
            #pragma unroll
            for (int i = 0; i < 2; i++) {
                float m = i ? a1 : a0;
                #pragma unroll
                for (int o = 16; o > 0; o >>= 1) m = fmaxf(m, __shfl_xor_sync(0xffffffffu, m, o));
                if (lane == 0) redM[(sg*2+i)*4 + (w & 3)] = m;
            }
            __syncthreads();
            if (tid < 8) {
                float m = fmaxf(fmaxf(redM[tid*4], redM[tid*4+1]), fmaxf(redM[tid*4+2], redM[tid*4+3]));
                mrow[tid] = m;
                g_pmax[(b*8 + tid)*8 + chunk] = m;
            }
            __syncthreads();
            float e0v = expf(a0 - mrow[sg*2+0]);
            float e1v = expf(a1 - mrow[sg*2+1]);
            g_escore[(size_t)(b*8 + sg*2+0)*1024 + n0 + nl] = e0v;
            g_escore[(size_t)(b*8 + sg*2+1)*1024 + n0 + nl] = e1v;
            attnT[nl*8 + sg*2+0] = e0v;
            attnT[nl*8 + sg*2+1] = e1v;
            #pragma unroll
            for (int i = 0; i < 2; i++) {
                float e = i ? e1v : e0v;
                #pragma unroll
                for (int o = 16; o > 0; o >>= 1) e += __shfl_xor_sync(0xffffffffu, e, o);
                if (lane == 0) redS[(sg*2+i)*4 + (w & 3)] = e;
            }
            __syncthreads();
            if (tid < 8)
                g_psum[(b*8 + tid)*8 + chunk] = redS[tid*4] + redS[tid*4+1] + redS[tid*4+2] + redS[tid*4+3];

            // exp·H partials: per n, 1 LDG + 1 broadcast LDS.128 + 4 FMA
            const int j = tid & 255, sh = tid >> 8;
            const float* hb = H + ((size_t)(b*16 + t)*1024 + n0) * 256;
            float acc[4] = {0.f,0.f,0.f,0.f};
            #pragma unroll 8
            for (int n = 0; n < 128; n++) {
                float hv = __ldg(&hb[(size_t)n*256 + j]);
                float4 e4 = *(const float4*)&attnT[n*8 + sh*4];
                acc[0] = fmaf(e4.x, hv, acc[0]);
                acc[1] = fmaf(e4.y, hv, acc[1]);
                acc[2] = fmaf(e4.z, hv, acc[2]);
                acc[3] = fmaf(e4.w, hv, acc[3]);
            }
            float* up = g_upart + (size_t)chunk * UP_PLANE;
            #pragma unroll
            for (int s = 0; s < 4; s++) up[(b*8 + sh*4 + s)*256 + j] = acc[s];
        }
        gridbar();

        // ---------- Phase C: gi partials, block-cooperative 16x128 tile (96 blocks) ----------
        {
            bool act = bid < 96;
            int tb = act ? bid : 0;
            const int ks = tb & 1, colT = (tb >> 1) % 6, rowT = (tb >> 1) / 6;
            const int m0 = rowT*16, c0 = colT*128, kb = ks*128;
            float* Ss = sm;              // flash-combined U tile k-major [128][17]
            float* Bs = sm + 2176;       // M2 fragment [32][132]
            float* ws = sm + 6400;       // [16][9]
            if (tid < 16) {
                int r = m0 + tid;
                float pm[8];
                #pragma unroll
                for (int c = 0; c < 8; c++) pm[c] = __ldcg(&g_pmax[r*8 + c]);
                float m = pm[0];
                #pragma unroll
                for (int c = 1; c < 8; c++) m = fmaxf(m, pm[c]);
                float S = 0.f;
                #pragma unroll
                for (int c = 0; c < 8; c++) S += __ldcg(&g_psum[r*8 + c]) * expf(pm[c] - m);
                float invS = 1.f / S;
                #pragma unroll
                for (int c = 0; c < 8; c++) ws[tid*9 + c] = expf(pm[c] - m) * invS;
            }
            __syncthreads();
            for (int i = tid; i < 2048; i += 512) {
                int r = i >> 7, k = i & 127;
                size_t idx = (size_t)(m0+r)*256 + kb + k;
                float v = 0.f;
                #pragma unroll
                for (int p = 0; p < 8; p++)
                    v = fmaf(__ldcg(&g_upart[(size_t)p*UP_PLANE + idx]), ws[r*9 + p], v);
                Ss[k*17 + r] = v;
            }
            const int row = tid & 15, cg = tid >> 4;
            float a0=0.f, a1=0.f, a2=0.f, a3=0.f;
            for (int k0 = 0; k0 < 128; k0 += 32) {
                __syncthreads();
                for (int i = tid; i < 4096; i += 512) {
                    int e = i >> 7, c = i & 127;
                    Bs[e*132 + c] = g_M2[(size_t)(c0+c)*256 + kb + k0 + e];
                }
                __syncthreads();
                #pragma unroll
                for (int e = 0; e < 32; e++) {
                    float a = Ss[(k0+e)*17 + row];
                    float4 b4 = *(const float4*)&Bs[e*132 + cg*4];
                    a0 = fmaf(a,b4.x,a0); a1 = fmaf(a,b4.y,a1);
                    a2 = fmaf(a,b4.z,a2); a3 = fmaf(a,b4.w,a3);
                }
            }
            int cb = c0 + cg*4;
            if (ks == 0) {
                #pragma unroll
                for (int p = 0; p < 8; p++) {
                    const float* bp = g_c2part + p * 768;
                    a0 += bp[cb]; a1 += bp[cb+1]; a2 += bp[cb+2]; a3 += bp[cb+3];
                }
            }
            if (act)
                *(float4*)&g_gi2[(size_t)ks*GI_PLANE + (m0+row)*768 + cb] = make_float4(a0,a1,a2,a3);
        }
        gridbar();

        // ---------- Phase D: GRU (once per element) + ffn1 partials + Beta writer ----------
        {
            const int colH = bid & 1, ks = (bid >> 1) & 7, rowT = bid >> 4;
            const int m0 = rowT*16, kb = ks*32, c0 = colH*128;
            float* Ss2 = sm;             // s2 tile k-major [32][17] = 544
            float* Bs  = sm + 544;       // W1 fragment [32][132] = 4224
            float* ws8 = sm + 4768;      // 8 beta weights for row bid
            {   // s2: one element per thread
                int r = tid >> 5, k = tid & 31, gr = m0 + r, d = kb + k;
                float gir = __ldcg(&g_gi2[gr*768 + d])       + __ldcg(&g_gi2[GI_PLANE + gr*768 + d]);
                float giz = __ldcg(&g_gi2[gr*768 + 256 + d]) + __ldcg(&g_gi2[GI_PLANE + gr*768 + 256 + d]);
                float gin = __ldcg(&g_gi2[gr*768 + 512 + d]) + __ldcg(&g_gi2[GI_PLANE + gr*768 + 512 + d]);
                float ghr = __ldcg(&g_qtgh2[gr*1024 + 256 + d]) + __ldcg(&g_qtgh2[QT_PLANE + gr*1024 + 256 + d]);
                float ghz = __ldcg(&g_qtgh2[gr*1024 + 512 + d]) + __ldcg(&g_qtgh2[QT_PLANE + gr*1024 + 512 + d]);
                float ghn = __ldcg(&g_qtgh2[gr*1024 + 768 + d]) + __ldcg(&g_qtgh2[QT_PLANE + gr*1024 + 768 + d]);
                float rg = sigm(gir + ghr);
                float z  = sigm(giz + ghz);
                float nn = tanhf(gin + rg * ghn);
                float s2 = (1.f - z) * nn + z * __ldcg(&g_slots[gr*256 + d]);
                Ss2[k*17 + r] = s2;
                if (colH == 0) g_s2[gr*256 + d] = s2;
            }
            if (tid < 8) {               // beta weights for row bid
                int r = bid;
                float pm[8];
                #pragma unroll
                for (int c = 0; c < 8; c++) pm[c] = __ldcg(&g_pmax[r*8 + c]);
                float m = pm[0];
                #pragma unroll
                for (int c = 1; c < 8; c++) m = fmaxf(m, pm[c]);
                float S = 0.f;
                #pragma unroll
                for (int c = 0; c < 8; c++) S += __ldcg(&g_psum[r*8 + c]) * expf(pm[c] - m);
                ws8[tid] = expf(pm[tid] - m) / S;
            }
            for (int i = tid; i < 4096; i += 512) {
                int e = i >> 7, c = i & 127;
                Bs[e*132 + c] = W1[(size_t)(c0+c)*256 + kb + e];
            }
            __syncthreads();
            if (tid < 256) {             // Beta writer: row bid, one float4 per thread
                float wv = ws8[tid >> 5];
                float4 v = __ldcg((const float4*)&g_escore[(size_t)bid*1024 + tid*4]);
                int bb = bid >> 3, l = bid & 7;
                *(float4*)&outB[(size_t)((bb*16 + t)*8 + l)*1024 + tid*4] =
                    make_float4(v.x*wv, v.y*wv, v.z*wv, v.w*wv);
            }
            const int row = tid & 15, cg = tid >> 4;
            float a0=0.f, a1=0.f, a2=0.f, a3=0.f;
            #pragma unroll
            for (int e = 0; e < 32; e++) {
                float a = Ss2[e*17 + row];
                float4 b4 = *(const float4*)&Bs[e*132 + cg*4];
                a0 = fmaf(a,b4.x,a0); a1 = fmaf(a,b4.y,a1);
                a2 = fmaf(a,b4.z,a2); a3 = fmaf(a,b4.w,a3);
            }
            int cb = c0 + cg*4;
            if (ks == 0) { a0 += b1[cb]; a1 += b1[cb+1]; a2 += b1[cb+2]; a3 += b1[cb+3]; }
            *(float4*)&g_h1p[(size_t)ks*H1_PLANE + (m0+row)*256 + cb] = make_float4(a0,a1,a2,a3);
        }
        gridbar();

        // ---------- Phase E1: ffn2 partials (relu-summed h1 tile @ W2 fragment) ----------
        {
            const int colH = bid & 1, ks = (bid >> 1) & 7, rowT = bid >> 4;
            const int m0 = rowT*16, kb = ks*32, c0 = colH*128;
            float* Sh = sm;              // relu(h1) tile k-major [32][17]
            float* Bs = sm + 544;        // W2 fragment [32][132]
            {   // one element per thread: relu of 8-plane sum
                int r = tid >> 5, k = tid & 31;
                size_t off = (size_t)(m0 + r)*256 + kb + k;
                float v = 0.f;
                #pragma unroll
                for (int p = 0; p < 8; p++) v += __ldcg(&g_h1p[(size_t)p*H1_PLANE + off]);
                Sh[k*17 + r] = fmaxf(v, 0.f);
            }
            for (int i = tid; i < 4096; i += 512) {
                int e = i >> 7, c = i & 127;
                Bs[e*132 + c] = W2[(size_t)(c0+c)*256 + kb + e];
            }
            __syncthreads();
            const int row = tid & 15, cg = tid >> 4;
            float a0=0.f, a1=0.f, a2=0.f, a3=0.f;
            #pragma unroll
            for (int e = 0; e < 32; e++) {
                float a = Sh[e*17 + row];
                float4 b4 = *(const float4*)&Bs[e*132 + cg*4];
                a0 = fmaf(a,b4.x,a0); a1 = fmaf(a,b4.y,a1);
                a2 = fmaf(a,b4.z,a2); a3 = fmaf(a,b4.w,a3);
            }
            int cb = c0 + cg*4;
            *(float4*)&g_h2p[(size_t)ks*H1_PLANE + (m0+row)*256 + cb] = make_float4(a0,a1,a2,a3);
        }
        gridbar();

        // ---------- Phase E2: sum partials + residual + LN (64 blocks, 2 rows) ----------
        {
            bool act = bid < 64;
            int rb = (act ? bid : 0) * 2;
            float* rs = sm;              // 16
            float* rq = sm + 16;         // 16
            const int w = tid >> 5, lane = tid & 31;
            const int rr = w >> 3, oct = w & 7;
            const int rowr = rb + rr, col = oct*32 + lane;
            size_t off = (size_t)rowr*256 + col;
            float x = 0.f;
            #pragma unroll
            for (int p = 0; p < 8; p++) x += __ldcg(&g_h2p[(size_t)p*H1_PLANE + off]);
            x += b2[col] + __ldcg(&g_s2[off]);
            float s = x, q = x*x;
            #pragma unroll
            for (int o = 16; o > 0; o >>= 1) {
                s += __shfl_xor_sync(0xffffffffu, s, o);
                q += __shfl_xor_sync(0xffffffffu, q, o);
            }
            __syncthreads();
            if (lane == 0) { rs[rr*8 + oct] = s; rq[rr*8 + oct] = q; }
            __syncthreads();
            float ts = 0.f, tq = 0.f;
            #pragma unroll
            for (int o = 0; o < 8; o++) { ts += rs[rr*8 + o]; tq += rq[rr*8 + o]; }
            float mean = ts * (1.f/256.f);
            float var  = tq * (1.f/256.f) - mean*mean;
            float inv  = rsqrtf(var + 1e-5f);
            if (act) {
                float y = (x - mean) * inv * lg[col] + lb[col];
                g_slots[off] = y;
                int bb = rowr >> 3, l = rowr & 7;
                outS[(size_t)((bb*16 + t)*8 + l)*256 + col] = y;
            }
        }
        gridbar();
    }
}

// ================= launcher =================
extern "C" void kernel_launch(void* const* d_in, const int* in_sizes, int n_in,
                              void* d_out, int out_size)
{
    const float* H    = (const float*)d_in[0];
    const float* eps  = (const float*)d_in[1];
    const float* mu   = (const float*)d_in[2];
    const float* ls   = (const float*)d_in[3];
    const float* Wq   = (const float*)d_in[4];
    const float* bq   = (const float*)d_in[5];
    const float* Wk   = (const float*)d_in[6];
    // d_in[7] = bk: row-constant in logits, cancels in softmax — provably unused.
    const float* Wv   = (const float*)d_in[8];
    const float* bv   = (const float*)d_in[9];
    const float* W_ih = (const float*)d_in[10];
    const float* b_ih = (const float*)d_in[11];
    const float* W_hh = (const float*)d_in[12];
    const float* b_hh = (const float*)d_in[13];
    const float* W1   = (const float*)d_in[14];
    const float* b1   = (const float*)d_in[15];
    const float* W2   = (const float*)d_in[16];
    const float* b2   = (const float*)d_in[17];
    const float* lng  = (const float*)d_in[18];
    const float* lnb  = (const float*)d_in[19];

    float* outS = (float*)d_out;
    float* outB = outS + S_ELEMS;

    pre_misc<<<376, 256>>>(eps, mu, ls, W_hh, bq, Wk, b_hh, W_ih, bv, b_ih);
    pre_gemm<<<dim3(8, 32), 256>>>(Wq, Wk, W_ih, Wv);
    mega_kernel<<<NB, 512>>>(H, W1, b1, W2, b2, lng, lnb, outS, outB);
}